// round 7
// baseline (speedup 1.0000x reference)
#include <cuda_runtime.h>

// Problem constants (N_ATOMS = 128, fixed by the reference)
#define NA      128
#define NSEG    7875          // sum_{i=0}^{124} (125 - i)
#define NPAIR   3938          // ceil(NSEG / 2)
#define OUTPB   16256         // n^2 - n  (all off-diagonal cells, row-major)
#define MAXB    512
#define SDIM    130           // padded symmetric matrix, zero border

// Scratch: per-batch padded symmetric segment-writhe matrix (~34.6 MB).
// Zero-initialized at module load. writhe writes valid (|i-j|>=2) cells in
// BOTH triangles; all other cells stay 0 forever.
__device__ float g_S[(size_t)MAXB * SDIM * SDIM];

// off(i) = number of segments with first index < i  (n = 128)
__device__ __forceinline__ int seg_off(int i) { return (i * (251 - i)) >> 1; }

// ---------------- packed f32x2 helpers (sm_100+ PTX) ----------------------
typedef unsigned long long u64;

__device__ __forceinline__ u64 pk(float lo, float hi)
{ u64 r; asm("mov.b64 %0,{%1,%2};" : "=l"(r) : "f"(lo), "f"(hi)); return r; }
__device__ __forceinline__ void upk(float& lo, float& hi, u64 v)
{ asm("mov.b64 {%0,%1},%2;" : "=f"(lo), "=f"(hi) : "l"(v)); }
__device__ __forceinline__ u64 f2add(u64 a, u64 b)
{ u64 r; asm("add.rn.f32x2 %0,%1,%2;" : "=l"(r) : "l"(a), "l"(b)); return r; }
__device__ __forceinline__ u64 f2sub(u64 a, u64 b)
{ u64 r; asm("sub.rn.f32x2 %0,%1,%2;" : "=l"(r) : "l"(a), "l"(b)); return r; }
__device__ __forceinline__ u64 f2mul(u64 a, u64 b)
{ u64 r; asm("mul.rn.f32x2 %0,%1,%2;" : "=l"(r) : "l"(a), "l"(b)); return r; }
__device__ __forceinline__ u64 f2fma(u64 a, u64 b, u64 c)
{ u64 r; asm("fma.rn.f32x2 %0,%1,%2,%3;" : "=l"(r) : "l"(a), "l"(b), "l"(c)); return r; }
__device__ __forceinline__ u64 f2abs(u64 a) { return a & 0x7FFFFFFF7FFFFFFFULL; }

#define DUPC(x) ((((u64)__float_as_uint(x)) << 32) | (u64)__float_as_uint(x))

// packed dot product
__device__ __forceinline__ u64 f2dot(u64 ax, u64 ay, u64 az, u64 bx, u64 by, u64 bz)
{ return f2fma(az, bz, f2fma(ay, by, f2mul(ax, bx))); }

// packed cross product
__device__ __forceinline__ void f2cross(u64 ax, u64 ay, u64 az,
                                        u64 bx, u64 by, u64 bz,
                                        u64& cx, u64& cy, u64& cz)
{
    cx = f2sub(f2mul(ay, bz), f2mul(az, by));
    cy = f2sub(f2mul(az, bx), f2mul(ax, bz));
    cz = f2sub(f2mul(ax, by), f2mul(ay, bx));
}

// packed branch-free asin (A&S 4.4.46), input q in [-1-eps, 1+eps]
__device__ __forceinline__ u64 f2asin(u64 q)
{
    const u64 ONE  = DUPC(1.0f);
    const u64 HALF = DUPC(0.5f);
    const u64 TINY = DUPC(1e-38f);
    const u64 PIH  = DUPC(1.5707963268f);

    const u64 a  = f2abs(q);
    u64 om = f2sub(ONE, a);
    om = f2mul(f2add(om, f2abs(om)), HALF);  // exact max(om, 0)
    om = f2add(om, TINY);                    // avoid 0 * inf
    float ol, oh; upk(ol, oh, om);
    const u64 rs = pk(rsqrtf(ol), rsqrtf(oh));
    const u64 s  = f2mul(om, rs);            // sqrt(om)

    u64 p = f2fma(a, DUPC(-0.0012624911f), DUPC(0.0066700901f));
    p = f2fma(a, p, DUPC(-0.0170881256f));
    p = f2fma(a, p, DUPC( 0.0308918810f));
    p = f2fma(a, p, DUPC(-0.0501743046f));
    p = f2fma(a, p, DUPC( 0.0889789874f));
    p = f2fma(a, p, DUPC(-0.2145988016f));
    p = f2fma(a, p, DUPC( 1.5707963050f));

    u64 res = f2sub(PIH, f2mul(s, p));
    // copysign from q, packed
    return (res & 0x7FFFFFFF7FFFFFFFULL) | (q & 0x8000000080000000ULL);
}

// -------------------------------------------------------------------------
// Kernel 1: writhe, 2 segments per thread via packed f32x2 arithmetic.
// Stores each value into BOTH triangles of padded S.
// -------------------------------------------------------------------------
__global__ __launch_bounds__(256) void writhe_kernel(const float* __restrict__ xyz)
{
    __shared__ float4 pt[NA];
    const int b = blockIdx.y;
    const float* x = xyz + (size_t)b * NA * 3;
    for (int t = threadIdx.x; t < NA; t += blockDim.x)
        pt[t] = make_float4(x[3 * t + 0], x[3 * t + 1], x[3 * t + 2], 0.0f);
    __syncthreads();

    const int tp = blockIdx.x * blockDim.x + threadIdx.x;
    const int sA = 2 * tp;
    if (sA >= NSEG) return;
    const bool hasB = (sA + 1 < NSEG);

    // invert sA -> (i, j)
    int i = (int)((251.0f - sqrtf(63001.0f - 8.0f * (float)sA)) * 0.5f);
    if (i < 0) i = 0;
    if (i > 124) i = 124;
    while (i < 124 && seg_off(i + 1) <= sA) i++;
    while (i > 0 && seg_off(i) > sA) i--;
    const int j = sA - seg_off(i) + i + 2;

    // segment B = next segment (row wrap), duplicate A when invalid
    int iB = (j < 126) ? i : i + 1;
    int jB = (j < 126) ? j + 1 : iB + 2;
    if (!hasB) { iB = i; jB = j; }

    const float4 A0 = pt[i],  A1 = pt[i + 1],  A2 = pt[j],  A3 = pt[j + 1];
    const float4 B0 = pt[iB], B1 = pt[iB + 1], B2 = pt[jB], B3 = pt[jB + 1];

    // packed point coords (lo = segment A, hi = segment B)
    const u64 P0x = pk(A0.x, B0.x), P0y = pk(A0.y, B0.y), P0z = pk(A0.z, B0.z);
    const u64 P1x = pk(A1.x, B1.x), P1y = pk(A1.y, B1.y), P1z = pk(A1.z, B1.z);
    const u64 P2x = pk(A2.x, B2.x), P2y = pk(A2.y, B2.y), P2z = pk(A2.z, B2.z);
    const u64 P3x = pk(A3.x, B3.x), P3y = pk(A3.y, B3.y), P3z = pk(A3.z, B3.z);

    // unnormalized directions
    const u64 d0x = f2sub(P2x, P0x), d0y = f2sub(P2y, P0y), d0z = f2sub(P2z, P0z);
    const u64 d1x = f2sub(P3x, P0x), d1y = f2sub(P3y, P0y), d1z = f2sub(P3z, P0z);
    const u64 d2x = f2sub(P2x, P1x), d2y = f2sub(P2y, P1y), d2z = f2sub(P2z, P1z);
    const u64 d3x = f2sub(P3x, P1x), d3y = f2sub(P3y, P1y), d3z = f2sub(P3z, P1z);

    u64 c0x, c0y, c0z, c1x, c1y, c1z, c2x, c2y, c2z, c3x, c3y, c3z;
    f2cross(d0x, d0y, d0z, d1x, d1y, d1z, c0x, c0y, c0z);
    f2cross(d1x, d1y, d1z, d3x, d3y, d3z, c1x, c1y, c1z);
    f2cross(d3x, d3y, d3z, d2x, d2y, d2z, c2x, c2y, c2z);
    f2cross(d2x, d2y, d2z, d0x, d0y, d0z, c3x, c3y, c3z);

    // sign: dot(axial, d0) == -(d2 . c0)
    const u64 dpp = f2dot(d2x, d2y, d2z, c0x, c0y, c0z);
    float dpA, dpB; upk(dpA, dpB, dpp);
    const float sgA = (dpA < 0.0f) ? 1.0f : ((dpA > 0.0f) ? -1.0f : 0.0f);
    const float sgB = (dpB < 0.0f) ? 1.0f : ((dpB > 0.0f) ? -1.0f : 0.0f);

    // norms -> rsqrt (scalar MUFU islands)
    const u64 n0 = f2dot(c0x, c0y, c0z, c0x, c0y, c0z);
    const u64 n1 = f2dot(c1x, c1y, c1z, c1x, c1y, c1z);
    const u64 n2 = f2dot(c2x, c2y, c2z, c2x, c2y, c2z);
    const u64 n3 = f2dot(c3x, c3y, c3z, c3x, c3y, c3z);
    float v0a, v0b, v1a, v1b, v2a, v2b, v3a, v3b;
    upk(v0a, v0b, n0); upk(v1a, v1b, n1); upk(v2a, v2b, n2); upk(v3a, v3b, n3);
    const u64 r0 = pk(rsqrtf(v0a), rsqrtf(v0b));
    const u64 r1 = pk(rsqrtf(v1a), rsqrtf(v1b));
    const u64 r2 = pk(rsqrtf(v2a), rsqrtf(v2b));
    const u64 r3 = pk(rsqrtf(v3a), rsqrtf(v3b));

    const u64 q0 = f2mul(f2mul(f2dot(c0x, c0y, c0z, c1x, c1y, c1z), r0), r1);
    const u64 q1 = f2mul(f2mul(f2dot(c1x, c1y, c1z, c2x, c2y, c2z), r1), r2);
    const u64 q2 = f2mul(f2mul(f2dot(c2x, c2y, c2z, c3x, c3y, c3z), r2), r3);
    const u64 q3 = f2mul(f2mul(f2dot(c3x, c3y, c3z, c0x, c0y, c0z), r3), r0);

    const u64 omega = f2add(f2add(f2asin(q0), f2asin(q1)),
                            f2add(f2asin(q2), f2asin(q3)));

    const u64 wrp = f2mul(omega, f2mul(pk(sgA, sgB), DUPC(0.15915494309189535f)));
    float wrA, wrB; upk(wrA, wrB, wrp);

    float* S = g_S + (size_t)b * SDIM * SDIM;
    S[(i + 1) * SDIM + (j + 1)] = wrA;
    S[(j + 1) * SDIM + (i + 1)] = wrA;
    if (hasB) {
        S[(iB + 1) * SDIM + (jB + 1)] = wrB;
        S[(jB + 1) * SDIM + (iB + 1)] = wrB;
    }
}

// -------------------------------------------------------------------------
// Kernel 2: row-staged stencil gather.
// Block = (batch b, 8 output rows r0..r0+7). Stages S rows r0..r0+8
// (contiguous 1170 floats) into smem; each warp emits one output row.
// -------------------------------------------------------------------------
__global__ __launch_bounds__(256) void gather_kernel(float* __restrict__ out)
{
    __shared__ float sm[9 * SDIM];
    const int b  = blockIdx.y;
    const int r0 = blockIdx.x * 8;

    const float* Srows = g_S + (size_t)b * SDIM * SDIM + (size_t)r0 * SDIM;
    for (int idx = threadIdx.x; idx < 9 * SDIM; idx += 256)
        sm[idx] = Srows[idx];                    // fully coalesced stream
    __syncthreads();

    const int w    = threadIdx.x >> 5;           // 0..7: output row within tile
    const int lane = threadIdx.x & 31;
    const int r    = r0 + w;
    const float* row0 = sm + w * SDIM;           // S[r]
    const float* row1 = sm + (w + 1) * SDIM;     // S[r+1]
    float* orow = out + (size_t)b * OUTPB + (size_t)r * 127;

    #pragma unroll
    for (int e = 0; e < 4; ++e) {
        const int cp = lane + 32 * e;
        if (cp < 127) {
            const int c = cp + (cp >= r ? 1 : 0);
            orow[cp] = row1[c + 1] + row1[c] + row0[c + 1] + row0[c];
        }
    }
}

// -------------------------------------------------------------------------
extern "C" void kernel_launch(void* const* d_in, const int* in_sizes, int n_in,
                              void* d_out, int out_size)
{
    const float* xyz = (const float*)d_in[0];
    int B = in_sizes[0] / (NA * 3);
    if (B > MAXB) B = MAXB;

    dim3 gw((NPAIR + 255) / 256, B);
    writhe_kernel<<<gw, 256>>>(xyz);

    dim3 gg(16, B);
    gather_kernel<<<gg, 256>>>((float*)d_out);
}

// round 8
// speedup vs baseline: 1.5432x; 1.5432x over previous
#include <cuda_runtime.h>

// Problem constants (N_ATOMS = 128, fixed by the reference)
#define NA      128
#define NSEG    7875          // sum_{i=0}^{124} (125 - i)
#define NQUADS  4064          // OUTPB / 4
#define OUTPB   16256         // n^2 - n  (all off-diagonal cells, row-major)
#define MAXB    512
#define SDIM    130           // padded symmetric matrix, zero border

// Scratch: per-batch padded symmetric segment-writhe matrix (~34.6 MB).
// Zero-initialized at module load. writhe writes valid (|i-j|>=2) cells in
// BOTH triangles; all other cells stay 0 forever.
__device__ float g_S[(size_t)MAXB * SDIM * SDIM];

// Branch-free asin via Abramowitz & Stegun 4.4.46 (|eps| ~ 1e-7 in float)
__device__ __forceinline__ float fast_asin(float x)
{
    const float a = fabsf(x);
    float p = fmaf(a, -0.0012624911f, 0.0066700901f);
    p = fmaf(a, p, -0.0170881256f);
    p = fmaf(a, p,  0.0308918810f);
    p = fmaf(a, p, -0.0501743046f);
    p = fmaf(a, p,  0.0889789874f);
    p = fmaf(a, p, -0.2145988016f);
    p = fmaf(a, p,  1.5707963050f);
    const float om = 1.0f - a;                       // >= 0 (input clamped)
    const float s  = om * rsqrtf(fmaxf(om, 1e-38f)); // sqrt(om) via MUFU
    return copysignf(1.5707963268f - s * p, x);
}

// -------------------------------------------------------------------------
// Kernel 1: writhe, 4 chained segments per thread (one row, j0..j0+3).
// Warp packing: warp 0 <-> row 0 (exactly 32 quads); warp p (1..62) packs
// rows (p, 125-p) whose quad counts sum to exactly 32. 63 warps per batch.
// Chain identities per j -> j+1:  d0 <- d1, d2 <- d3, c3 <- -c1, r3 <- r1.
// -------------------------------------------------------------------------
__global__ __launch_bounds__(256) void writhe_kernel(const float* __restrict__ xyz)
{
    __shared__ float4 pt[NA];
    const int b = blockIdx.y;
    const float* x = xyz + (size_t)b * NA * 3;
    for (int t = threadIdx.x; t < NA; t += blockDim.x)
        pt[t] = make_float4(x[3 * t + 0], x[3 * t + 1], x[3 * t + 2], 0.0f);
    __syncthreads();

    const int warp = threadIdx.x >> 5;
    const int lane = threadIdx.x & 31;
    const int p    = blockIdx.x * 8 + warp;          // 0..63; 63 is empty
    if (p > 62) return;

    const int iA = p;
    const int iB = (p == 0) ? 0 : (125 - p);
    const int qA = (125 - iA + 3) >> 2;              // quads in row A (<=32)

    const bool inA = (lane < qA);
    const int  i   = inA ? iA : iB;
    const int  m   = inA ? lane : (lane - qA);
    const int  j0  = i + 2 + 4 * m;

    const float4 Q0 = pt[i];
    const float4 Q1 = pt[i + 1];
    float4 Pj[5];
    #pragma unroll
    for (int k = 0; k < 5; ++k) Pj[k] = pt[min(j0 + k, 127)];

    // chain state: d0 = P_j - P_i, d2 = P_j - P_{i+1}, c3 = d2 x d0
    float d0x = Pj[0].x - Q0.x, d0y = Pj[0].y - Q0.y, d0z = Pj[0].z - Q0.z;
    float d2x = Pj[0].x - Q1.x, d2y = Pj[0].y - Q1.y, d2z = Pj[0].z - Q1.z;
    float c3x = d2y * d0z - d2z * d0y;
    float c3y = d2z * d0x - d2x * d0z;
    float c3z = d2x * d0y - d2y * d0x;
    float r3  = rsqrtf(c3x * c3x + c3y * c3y + c3z * c3z);

    float* S = g_S + (size_t)b * SDIM * SDIM;

    #pragma unroll
    for (int k = 0; k < 4; ++k) {
        const int j = j0 + k;
        const float4 Pn = Pj[k + 1];

        const float d1x = Pn.x - Q0.x, d1y = Pn.y - Q0.y, d1z = Pn.z - Q0.z;
        const float d3x = Pn.x - Q1.x, d3y = Pn.y - Q1.y, d3z = Pn.z - Q1.z;

        // c0 = d0 x d1, c1 = d1 x d3, c2 = d3 x d2
        const float c0x = d0y * d1z - d0z * d1y;
        const float c0y = d0z * d1x - d0x * d1z;
        const float c0z = d0x * d1y - d0y * d1x;

        const float c1x = d1y * d3z - d1z * d3y;
        const float c1y = d1z * d3x - d1x * d3z;
        const float c1z = d1x * d3y - d1y * d3x;

        const float c2x = d3y * d2z - d3z * d2y;
        const float c2y = d3z * d2x - d3x * d2z;
        const float c2z = d3x * d2y - d3y * d2x;

        // sign: dot(axial, d0) == -(d2 . c0)
        const float dp = d2x * c0x + d2y * c0y + d2z * c0z;
        const float sg = (dp < 0.0f) ? 1.0f : ((dp > 0.0f) ? -1.0f : 0.0f);

        const float r0 = rsqrtf(c0x * c0x + c0y * c0y + c0z * c0z);
        const float r1 = rsqrtf(c1x * c1x + c1y * c1y + c1z * c1z);
        const float r2 = rsqrtf(c2x * c2x + c2y * c2y + c2z * c2z);

        float q0 = (c0x * c1x + c0y * c1y + c0z * c1z) * r0 * r1;
        float q1 = (c1x * c2x + c1y * c2y + c1z * c2z) * r1 * r2;
        float q2 = (c2x * c3x + c2y * c3y + c2z * c3z) * r2 * r3;
        float q3 = (c3x * c0x + c3y * c0y + c3z * c0z) * r3 * r0;

        q0 = fminf(fmaxf(q0, -1.0f), 1.0f);
        q1 = fminf(fmaxf(q1, -1.0f), 1.0f);
        q2 = fminf(fmaxf(q2, -1.0f), 1.0f);
        q3 = fminf(fmaxf(q3, -1.0f), 1.0f);

        const float omega = fast_asin(q0) + fast_asin(q1) +
                            fast_asin(q2) + fast_asin(q3);
        const float wr = omega * sg * 0.15915494309189535f; // 1/(2*pi)

        if (j <= 126) {
            S[(i + 1) * SDIM + (j + 1)] = wr;
            S[(j + 1) * SDIM + (i + 1)] = wr;
        }

        // rotate chain state
        d0x = d1x;  d0y = d1y;  d0z = d1z;
        d2x = d3x;  d2y = d3y;  d2z = d3z;
        c3x = -c1x; c3y = -c1y; c3z = -c1z;
        r3  = r1;
    }
}

// -------------------------------------------------------------------------
// Kernel 2: streaming 2x2 stencil, float4 stores (4 outputs per thread).
// out[b, k], k <-> (r, c) row-major off-diagonal:
//   out = S[r][c] + S[r][c-1] + S[r-1][c] + S[r-1][c-1]  (padded coords +1)
// -------------------------------------------------------------------------
__global__ __launch_bounds__(256) void gather_kernel(float* __restrict__ out)
{
    const int q = blockIdx.x * blockDim.x + threadIdx.x;
    const int b = blockIdx.y;
    if (q >= NQUADS) return;

    const float* S = g_S + (size_t)b * SDIM * SDIM;

    float v[4];
    #pragma unroll
    for (int m = 0; m < 4; ++m) {
        const int k  = 4 * q + m;
        const int r  = k / 127;
        const int cp = k - r * 127;
        const int c  = cp + (cp >= r ? 1 : 0);
        const float* row1 = S + (r + 1) * SDIM;
        const float* row0 = S + r * SDIM;
        v[m] = row1[c + 1] + row1[c] + row0[c + 1] + row0[c];
    }

    float4* outq = (float4*)(out + (size_t)b * OUTPB);
    outq[q] = make_float4(v[0], v[1], v[2], v[3]);
}

// -------------------------------------------------------------------------
extern "C" void kernel_launch(void* const* d_in, const int* in_sizes, int n_in,
                              void* d_out, int out_size)
{
    const float* xyz = (const float*)d_in[0];
    int B = in_sizes[0] / (NA * 3);
    if (B > MAXB) B = MAXB;

    dim3 gw(8, B);                      // 8 blocks x 8 warps = 64 warps (63 used)
    writhe_kernel<<<gw, 256>>>(xyz);

    dim3 gg((NQUADS + 255) / 256, B);
    gather_kernel<<<gg, 256>>>((float*)d_out);
}